// round 4
// baseline (speedup 1.0000x reference)
#include <cuda_runtime.h>
#include <cstdint>
#include <cmath>

#define ZDIM 8192
#define QP   2016
#define NOUT 448

// ===================== device globals (no allocation) =====================
static __device__ float g_B0t[64 * 4160];     // out0 weights [w][k], prescaled + tf32-rounded
static __device__ float g_B6t[64 * 2016];     // out2 weights [w][q]
static __device__ float g_B3t[64 * 4096];     // out1 weights [w][q=(u*64+m)], * 1/64
static __device__ unsigned short g_uv[QP];    // packed (u | t<<8)

// ===================== helpers =====================
__device__ __forceinline__ uint32_t rna(float f) {
    uint32_t r; asm("cvt.rna.tf32.f32 %0, %1;" : "=r"(r) : "f"(f)); return r;
}
__device__ __forceinline__ void mma8(float* c, const uint32_t* a, const uint32_t* b) {
    asm volatile("mma.sync.aligned.m16n8k8.row.col.f32.tf32.tf32.f32 "
        "{%0,%1,%2,%3}, {%4,%5,%6,%7}, {%8,%9}, {%0,%1,%2,%3};"
        : "+f"(c[0]), "+f"(c[1]), "+f"(c[2]), "+f"(c[3])
        : "r"(a[0]), "r"(a[1]), "r"(a[2]), "r"(a[3]), "r"(b[0]), "r"(b[1]));
}

// ===================== setup kernels =====================
__global__ void init_tables_kernel() {
    int u = threadIdx.x;
    if (u < 63) {
        int idx = u * 63 - (u * (u - 1)) / 2;
        for (int v = u + 1; v < 64; ++v) {
            g_uv[idx] = (unsigned short)(u | (v << 8));
            ++idx;
        }
    }
}

__global__ void prep_w_kernel(const float* __restrict__ w1, const float* __restrict__ w2,
                              const float* __restrict__ w3, const float* __restrict__ w4,
                              const float* __restrict__ w5, const float* __restrict__ w6,
                              float c1, float c2, float c5s, float c6s) {
    int i = blockIdx.x * blockDim.x + threadIdx.x;
    const int N0 = 64 * 4160, N1 = 64 * 2016, N2 = 64 * 4096;
    if (i < N0) {
        int w = i / 4160, k = i - w * 4160;
        float v;
        if (k < 2016)      v = c1  * w1[k * 64 + w];
        else if (k < 2080) v = c2  * w2[(k - 2016) * 64 + w];
        else if (k < 4096) v = c2  * w4[(k - 2080) * 64 + w];
        else               v = c5s * w5[(k - 4096) * 64 + w];
        g_B0t[i] = __uint_as_float(rna(v));
    } else if (i < N0 + N1) {
        int j = i - N0;
        int w = j / 2016, q = j - w * 2016;
        g_B6t[j] = __uint_as_float(rna(c6s * w6[q * 64 + w]));
    } else if (i < N0 + N1 + N2) {
        int j = i - N0 - N1;
        int w = j >> 12, q = j & 4095;
        int u = q >> 6, m = q & 63;
        g_B3t[j] = __uint_as_float(rna(0.015625f * w3[u * 4096 + m * 64 + w]));
    }
}

// ===================== fused feature + tf32 mma.sync GEMM =====================
// CTA: 128 z-rows x 64 w-cols. 8 warps, warp tile 32x32 (warps 4M x 2N).
// EPI 0: out0, K split in 2 halves of 2080 (blockIdx.y), atomicAdd epilogue.
// EPI 1: out1, K=4096 features s_u * v_{m,kp}, kp=blockIdx.y, direct store.
// EPI 2: out2, K=2016 cross-product component kp=blockIdx.y, direct store.
template<int EPI>
__global__ __launch_bounds__(256) void fused_kernel(const float* __restrict__ x,
                                                    float* __restrict__ out) {
    constexpr int KTOT = (EPI == 0) ? 2080 : (EPI == 1 ? 4096 : 2016);
    constexpr int NCH  = KTOT / 32;
    constexpr int LDB  = (EPI == 0) ? 4160 : (EPI == 1 ? 4096 : 2016);
    constexpr int XC   = (EPI == 2) ? 192 : 256;
    constexpr int XST  = XC + 1;

    extern __shared__ __align__(16) char dsm[];
    float* As = (float*)dsm;                                   // [128][36]
    float* Bs = (float*)(dsm + 128 * 36 * 4);                  // [64][36]
    float* xs = (float*)(dsm + 128 * 36 * 4 + 64 * 36 * 4);    // [128][XST]
    unsigned short* uvs = (unsigned short*)(xs + 128 * XST);   // [2016] (EPI 0,2)

    const float* Bsrc = (EPI == 0) ? g_B0t : (EPI == 1 ? g_B3t : g_B6t);

    int tid = threadIdx.x, lane = tid & 31, wid = tid >> 5;
    int warpM = wid & 3, warpN = wid >> 2;
    int g = lane >> 2, q4 = lane & 3;
    int z0 = blockIdx.x * 128;
    int kz = blockIdx.y;                       // EPI0: K half; EPI1/2: component kp
    int kofs = (EPI == 0) ? kz * 2080 : 0;

    // ---- stage x tile ----
    if (EPI == 2) {
        for (int idx = tid; idx < 128 * 192; idx += 256) {
            int r = idx / 192, cc = idx - r * 192;
            xs[r * XST + cc] = x[(size_t)(z0 + r) * 256 + 64 + cc];
        }
    } else {
        #pragma unroll 4
        for (int j = 0; j < 128; ++j)
            xs[j * XST + tid] = x[(size_t)(z0 + j) * 256 + tid];
    }
    if (EPI != 1) {
        for (int i = tid; i < QP; i += 256) uvs[i] = g_uv[i];
    }

    int row = tid >> 1, h = tid & 1;
    const float* xr = xs + row * XST;

    // prefetch B chunk 0
    float4 rb[2];
    #pragma unroll
    for (int t = 0; t < 2; ++t) {
        int f4 = tid + t * 256; int br = f4 >> 3, c4 = f4 & 7;
        rb[t] = *(const float4*)(Bsrc + (size_t)br * LDB + kofs + c4 * 4);
    }

    float acc[2][4][4];
    #pragma unroll
    for (int mt = 0; mt < 2; ++mt)
        #pragma unroll
        for (int nt = 0; nt < 4; ++nt)
            #pragma unroll
            for (int j = 0; j < 4; ++j) acc[mt][nt][j] = 0.0f;

    __syncthreads();

    for (int c = 0; c < NCH; ++c) {
        // ---- stage B tile [64][32] ----
        #pragma unroll
        for (int t = 0; t < 2; ++t) {
            int f4 = tid + t * 256; int br = f4 >> 3, c4 = f4 & 7;
            *(float4*)(Bs + br * 36 + c4 * 4) = rb[t];
        }
        // ---- generate 16 features -> A tile ----
        int kbase = kofs + c * 32 + h * 16;
        uint32_t fr[16];
        #pragma unroll
        for (int i = 0; i < 16; ++i) {
            int k = kbase + i;
            float f;
            if (EPI == 0) {
                if (k < 2016) {
                    int uv = uvs[k];
                    f = xr[uv & 255] * xr[uv >> 8];
                } else if (k < 2080) {
                    float s = xr[k - 2016]; f = s * s;
                } else if (k < 4096) {
                    int uv = uvs[k - 2080];
                    const float* a = xr + 64 + 3 * (uv & 255);
                    const float* b = xr + 64 + 3 * (uv >> 8);
                    f = a[0] * b[0] + a[1] * b[1] + a[2] * b[2];
                } else {
                    const float* a = xr + 64 + 3 * (k - 4096);
                    f = a[0] * a[0] + a[1] * a[1] + a[2] * a[2];
                }
            } else if (EPI == 1) {
                int u = k >> 6, m = k & 63;
                f = xr[u] * xr[64 + 3 * m + kz];
            } else {
                int uv = uvs[k];
                const float* a = xr + 3 * (uv & 255);
                const float* b = xr + 3 * (uv >> 8);
                int ca = (kz + 1) % 3, cb = (kz + 2) % 3;
                f = a[ca] * b[cb] - a[cb] * b[ca];
            }
            fr[i] = rna(f);
        }
        #pragma unroll
        for (int j = 0; j < 4; ++j) {
            uint4 v4 = make_uint4(fr[4*j], fr[4*j+1], fr[4*j+2], fr[4*j+3]);
            *(uint4*)(As + row * 36 + h * 16 + 4 * j) = v4;
        }
        // prefetch next B
        if (c + 1 < NCH) {
            #pragma unroll
            for (int t = 0; t < 2; ++t) {
                int f4 = tid + t * 256; int br = f4 >> 3, c4 = f4 & 7;
                rb[t] = *(const float4*)(Bsrc + (size_t)br * LDB + kofs + (c + 1) * 32 + c4 * 4);
            }
        }
        __syncthreads();

        // ---- mma: 4 k-steps of 8 ----
        #pragma unroll
        for (int k8 = 0; k8 < 4; ++k8) {
            uint32_t a[2][4], b[4][2];
            #pragma unroll
            for (int mt = 0; mt < 2; ++mt) {
                const uint32_t* ap = (const uint32_t*)As + (warpM * 32 + mt * 16) * 36 + k8 * 8;
                a[mt][0] = ap[g * 36 + q4];
                a[mt][1] = ap[(g + 8) * 36 + q4];
                a[mt][2] = ap[g * 36 + q4 + 4];
                a[mt][3] = ap[(g + 8) * 36 + q4 + 4];
            }
            #pragma unroll
            for (int nt = 0; nt < 4; ++nt) {
                const uint32_t* bp = (const uint32_t*)Bs + (warpN * 32 + nt * 8 + g) * 36 + k8 * 8;
                b[nt][0] = bp[q4];
                b[nt][1] = bp[q4 + 4];
            }
            #pragma unroll
            for (int mt = 0; mt < 2; ++mt)
                #pragma unroll
                for (int nt = 0; nt < 4; ++nt)
                    mma8(acc[mt][nt], a[mt], b[nt]);
        }
        __syncthreads();
    }

    // ---- epilogue ----
    #pragma unroll
    for (int mt = 0; mt < 2; ++mt) {
        int za = z0 + warpM * 32 + mt * 16 + g;
        int zb = za + 8;
        #pragma unroll
        for (int nt = 0; nt < 4; ++nt) {
            int col = warpN * 32 + nt * 8 + q4 * 2;
            if (EPI == 0) {
                atomicAdd(out + (size_t)za * NOUT + col,     acc[mt][nt][0]);
                atomicAdd(out + (size_t)za * NOUT + col + 1, acc[mt][nt][1]);
                atomicAdd(out + (size_t)zb * NOUT + col,     acc[mt][nt][2]);
                atomicAdd(out + (size_t)zb * NOUT + col + 1, acc[mt][nt][3]);
            } else if (EPI == 1) {
                out[(size_t)za * NOUT + 64 + col * 3 + kz]       = acc[mt][nt][0];
                out[(size_t)za * NOUT + 64 + (col + 1) * 3 + kz] = acc[mt][nt][1];
                out[(size_t)zb * NOUT + 64 + col * 3 + kz]       = acc[mt][nt][2];
                out[(size_t)zb * NOUT + 64 + (col + 1) * 3 + kz] = acc[mt][nt][3];
            } else {
                out[(size_t)za * NOUT + 256 + col * 3 + kz]       = acc[mt][nt][0];
                out[(size_t)za * NOUT + 256 + (col + 1) * 3 + kz] = acc[mt][nt][1];
                out[(size_t)zb * NOUT + 256 + col * 3 + kz]       = acc[mt][nt][2];
                out[(size_t)zb * NOUT + 256 + (col + 1) * 3 + kz] = acc[mt][nt][3];
            }
        }
    }
}

// ===================== launch =====================
extern "C" void kernel_launch(void* const* d_in, const int* in_sizes, int n_in,
                              void* d_out, int out_size) {
    const float* x  = (const float*)d_in[0];
    const float* w1 = (const float*)d_in[1];
    const float* w2 = (const float*)d_in[2];
    const float* w3 = (const float*)d_in[3];
    const float* w4 = (const float*)d_in[4];
    const float* w5 = (const float*)d_in[5];
    const float* w6 = (const float*)d_in[6];
    float* out = (float*)d_out;

    float c1  = (float)sqrt(1.0 / 4160.0);     // C1
    float c2  = (float)sqrt(1.0 / 12480.0);    // C2 == C4/sqrt(3)
    float c5s = (float)sqrt(1.0 / 62400.0);    // C5/sqrt(3)
    float c6s = (float)sqrt(1.0 / 4032.0);     // C6/sqrt(6)

    const int TILES = 128 * 36 * 4 + 64 * 36 * 4;          // As + Bs = 27648
    const int SM0 = TILES + 128 * 257 * 4 + QP * 2;        // 163,264
    const int SM1 = TILES + 128 * 257 * 4;                 // 159,232
    const int SM2 = TILES + 128 * 193 * 4 + QP * 2;        // 130,496
    cudaFuncSetAttribute(fused_kernel<0>, cudaFuncAttributeMaxDynamicSharedMemorySize, SM0);
    cudaFuncSetAttribute(fused_kernel<1>, cudaFuncAttributeMaxDynamicSharedMemorySize, SM1);
    cudaFuncSetAttribute(fused_kernel<2>, cudaFuncAttributeMaxDynamicSharedMemorySize, SM2);

    cudaMemsetAsync(d_out, 0, (size_t)out_size * sizeof(float));
    init_tables_kernel<<<1, 64>>>();
    const int NTOT = 64 * 4160 + 64 * 2016 + 64 * 4096;
    prep_w_kernel<<<(NTOT + 255) / 256, 256>>>(w1, w2, w3, w4, w5, w6, c1, c2, c5s, c6s);

    fused_kernel<0><<<dim3(64, 2), 256, SM0>>>(x, out);   // out0 (split-K = 2)
    fused_kernel<1><<<dim3(64, 3), 256, SM1>>>(x, out);   // out1 (3 components)
    fused_kernel<2><<<dim3(64, 3), 256, SM2>>>(x, out);   // out2 (3 components)
}

// round 5
// speedup vs baseline: 1.0065x; 1.0065x over previous
#include <cuda_runtime.h>
#include <cstdint>
#include <cmath>

#define ZDIM 8192
#define QP   2016
#define NOUT 448

// ===================== device globals (no allocation) =====================
static __device__ float g_B0t[64 * 4160];          // out0 weights [w][k], prescaled + tf32
static __device__ float g_B6t[64 * 2016];          // out2 weights [w][q], prescaled + tf32
static __device__ float g_B3p[4096 * 64];          // out1 weights [n=(m*64+w)][u], tf32
static __device__ float g_T[(size_t)ZDIM * 4096];  // T = s @ w3 scratch [z][m*64+w]
static __device__ unsigned short g_uv[QP];         // packed (u | t<<8)

// ===================== helpers =====================
__device__ __forceinline__ uint32_t rna(float f) {
    uint32_t r; asm("cvt.rna.tf32.f32 %0, %1;" : "=r"(r) : "f"(f)); return r;
}
__device__ __forceinline__ float u2f(uint32_t u) { return __uint_as_float(u); }
__device__ __forceinline__ void mma8(float* c, const uint32_t* a, const uint32_t* b) {
    asm volatile("mma.sync.aligned.m16n8k8.row.col.f32.tf32.tf32.f32 "
        "{%0,%1,%2,%3}, {%4,%5,%6,%7}, {%8,%9}, {%0,%1,%2,%3};"
        : "+f"(c[0]), "+f"(c[1]), "+f"(c[2]), "+f"(c[3])
        : "r"(a[0]), "r"(a[1]), "r"(a[2]), "r"(a[3]), "r"(b[0]), "r"(b[1]));
}

// ===================== setup kernels =====================
__global__ void init_tables_kernel() {
    int u = threadIdx.x;
    if (u < 63) {
        int idx = u * 63 - (u * (u - 1)) / 2;
        for (int v = u + 1; v < 64; ++v) {
            g_uv[idx] = (unsigned short)(u | (v << 8));
            ++idx;
        }
    }
}

__global__ void prep_w_kernel(const float* __restrict__ w1, const float* __restrict__ w2,
                              const float* __restrict__ w3, const float* __restrict__ w4,
                              const float* __restrict__ w5, const float* __restrict__ w6,
                              float c1, float c2, float c5s, float c6s) {
    int i = blockIdx.x * blockDim.x + threadIdx.x;
    const int N0 = 64 * 4160, N1 = 64 * 2016, N2 = 4096 * 64;
    if (i < N0) {
        int w = i / 4160, k = i - w * 4160;
        float v;
        if (k < 2016)      v = c1  * w1[k * 64 + w];
        else if (k < 2080) v = c2  * w2[(k - 2016) * 64 + w];
        else if (k < 4096) v = c2  * w4[(k - 2080) * 64 + w];
        else               v = c5s * w5[(k - 4096) * 64 + w];
        g_B0t[i] = u2f(rna(v));
    } else if (i < N0 + N1) {
        int j = i - N0;
        int w = j / 2016, q = j - w * 2016;
        g_B6t[j] = u2f(rna(c6s * w6[q * 64 + w]));
    } else if (i < N0 + N1 + N2) {
        int j = i - N0 - N1;
        int n = j >> 6, u = j & 63;                  // n = m*64+w
        g_B3p[j] = u2f(rna(w3[(size_t)u * 4096 + n]));
    }
}

// ===================== main fused kernel: out0 (y=0,1: K halves) + out2 (y=2,3,4: components) =====
// CTA 128z x 64w, 8 warps 4M x 2N, warp tile 32x32. Single-sync double-buffered pipeline;
// SMEM tiles stored column-interleaved so fragments load as ld.shared.v2.
__global__ __launch_bounds__(256) void main_kernel(const float* __restrict__ x,
                                                   float* __restrict__ out) {
    extern __shared__ __align__(16) float dsm[];
    float* As = dsm;                                 // [2][128][36]
    float* Bs = dsm + 2 * 128 * 36;                  // [2][64][36]
    float* xs = Bs + 2 * 64 * 36;                    // [128][257]
    unsigned short* uvs = (unsigned short*)(xs + 128 * 257);

    const int tid = threadIdx.x, lane = tid & 31, wid = tid >> 5;
    const int warpM = wid & 3, warpN = wid >> 2;
    const int g = lane >> 2, q4 = lane & 3;
    const int z0 = blockIdx.x * 128;
    const int y = blockIdx.y;
    const bool m0 = (y < 2);
    const int kz = m0 ? y : (y - 2);
    const int kofs = m0 ? kz * 2080 : 0;
    const int NCH = m0 ? 65 : 63;
    const int LDB = m0 ? 4160 : 2016;
    const float* Bsrc = m0 ? g_B0t : g_B6t;
    const int ca = (kz + 1) % 3, cb = (kz + 2) % 3;  // cross components (mode 2)

    // ---- stage x tile + pair table ----
    #pragma unroll 4
    for (int j = 0; j < 128; ++j)
        xs[j * 257 + tid] = x[(size_t)(z0 + j) * 256 + tid];
    for (int i = tid; i < QP; i += 256) uvs[i] = g_uv[i];

    const int row = tid >> 1, h = tid & 1;
    const float* xr = xs + row * 257;
    const int brow = tid >> 2, bseg = tid & 3;
    const float* bbase = Bsrc + (size_t)brow * LDB + kofs + bseg * 8;

    float acc[2][4][4];
    #pragma unroll
    for (int mt = 0; mt < 2; ++mt)
        #pragma unroll
        for (int nt = 0; nt < 4; ++nt)
            #pragma unroll
            for (int j = 0; j < 4; ++j) acc[mt][nt][j] = 0.0f;

    __syncthreads();

    uint32_t fr[16];
    float4 rb0, rb1;

    // ---- feature generation into registers ----
    #define GEN(CC) do {                                                        \
        int kbase = kofs + (CC) * 32 + h * 16;                                  \
        _Pragma("unroll")                                                       \
        for (int i = 0; i < 16; ++i) {                                          \
            int k = kbase + i;                                                  \
            float f;                                                            \
            if (m0) {                                                           \
                if (k < 2016) {                                                 \
                    int uv = uvs[k];                                            \
                    f = xr[uv & 255] * xr[uv >> 8];                             \
                } else if (k < 2080) {                                          \
                    float s = xr[k - 2016]; f = s * s;                          \
                } else if (k < 4096) {                                          \
                    int uv = uvs[k - 2080];                                     \
                    const float* a = xr + 64 + 3 * (uv & 255);                  \
                    const float* b = xr + 64 + 3 * (uv >> 8);                   \
                    f = a[0] * b[0] + a[1] * b[1] + a[2] * b[2];                \
                } else {                                                        \
                    const float* a = xr + 64 + 3 * (k - 4096);                  \
                    f = a[0] * a[0] + a[1] * a[1] + a[2] * a[2];                \
                }                                                               \
            } else {                                                            \
                int uv = uvs[k];                                                \
                const float* a = xr + 64 + 3 * (uv & 255);                      \
                const float* b = xr + 64 + 3 * (uv >> 8);                       \
                f = a[ca] * b[cb] - a[cb] * b[ca];                              \
            }                                                                   \
            fr[i] = rna(f);                                                     \
        }                                                                       \
    } while (0)

    // ---- store regs -> SMEM buffers (interleaved pair layout) ----
    #define STORE(CC) do {                                                      \
        int buf = (CC) & 1;                                                     \
        float* ap = As + buf * (128 * 36) + row * 36 + h * 16;                  \
        _Pragma("unroll")                                                       \
        for (int j = 0; j < 4; ++j)                                             \
            *(float2*)(ap + j * 2) = make_float2(u2f(fr[j]), u2f(fr[j + 4]));   \
        _Pragma("unroll")                                                       \
        for (int j = 0; j < 4; ++j)                                             \
            *(float2*)(ap + 8 + j * 2) = make_float2(u2f(fr[8 + j]), u2f(fr[12 + j])); \
        float* bp = Bs + buf * (64 * 36) + brow * 36 + bseg * 8;                \
        *(float2*)(bp + 0) = make_float2(rb0.x, rb1.x);                         \
        *(float2*)(bp + 2) = make_float2(rb0.y, rb1.y);                         \
        *(float2*)(bp + 4) = make_float2(rb0.z, rb1.z);                         \
        *(float2*)(bp + 6) = make_float2(rb0.w, rb1.w);                         \
    } while (0)

    // prologue: chunk 0
    GEN(0);
    rb0 = *(const float4*)(bbase);
    rb1 = *(const float4*)(bbase + 4);
    STORE(0);
    __syncthreads();

    for (int c = 0; c < NCH; ++c) {
        bool more = (c + 1 < NCH);
        if (more) {
            rb0 = *(const float4*)(bbase + (c + 1) * 32);
            rb1 = *(const float4*)(bbase + (c + 1) * 32 + 4);
            GEN(c + 1);
        }
        {
            const float* Ab = As + (c & 1) * (128 * 36) + (warpM * 32) * 36;
            const float* Bb = Bs + (c & 1) * (64 * 36) + (warpN * 32) * 36;
            #pragma unroll
            for (int k8 = 0; k8 < 4; ++k8) {
                uint32_t a[2][4], b[4][2];
                #pragma unroll
                for (int mt = 0; mt < 2; ++mt) {
                    float2 lo = *(const float2*)(Ab + (mt * 16 + g) * 36 + k8 * 8 + q4 * 2);
                    float2 hi = *(const float2*)(Ab + (mt * 16 + 8 + g) * 36 + k8 * 8 + q4 * 2);
                    a[mt][0] = __float_as_uint(lo.x); a[mt][1] = __float_as_uint(hi.x);
                    a[mt][2] = __float_as_uint(lo.y); a[mt][3] = __float_as_uint(hi.y);
                }
                #pragma unroll
                for (int nt = 0; nt < 4; ++nt) {
                    float2 bv = *(const float2*)(Bb + (nt * 8 + g) * 36 + k8 * 8 + q4 * 2);
                    b[nt][0] = __float_as_uint(bv.x); b[nt][1] = __float_as_uint(bv.y);
                }
                #pragma unroll
                for (int mt = 0; mt < 2; ++mt)
                    #pragma unroll
                    for (int nt = 0; nt < 4; ++nt)
                        mma8(acc[mt][nt], a[mt], b[nt]);
            }
        }
        if (more) STORE(c + 1);
        __syncthreads();
    }

    // ---- epilogue ----
    #pragma unroll
    for (int mt = 0; mt < 2; ++mt) {
        int za = z0 + warpM * 32 + mt * 16 + g;
        int zb = za + 8;
        #pragma unroll
        for (int nt = 0; nt < 4; ++nt) {
            int col = warpN * 32 + nt * 8 + q4 * 2;
            if (m0) {
                atomicAdd(out + (size_t)za * NOUT + col,     acc[mt][nt][0]);
                atomicAdd(out + (size_t)za * NOUT + col + 1, acc[mt][nt][1]);
                atomicAdd(out + (size_t)zb * NOUT + col,     acc[mt][nt][2]);
                atomicAdd(out + (size_t)zb * NOUT + col + 1, acc[mt][nt][3]);
            } else {
                out[(size_t)za * NOUT + 256 + col * 3 + kz]       = acc[mt][nt][0];
                out[(size_t)za * NOUT + 256 + (col + 1) * 3 + kz] = acc[mt][nt][1];
                out[(size_t)zb * NOUT + 256 + col * 3 + kz]       = acc[mt][nt][2];
                out[(size_t)zb * NOUT + 256 + (col + 1) * 3 + kz] = acc[mt][nt][3];
            }
        }
    }
    #undef GEN
    #undef STORE
}

// ===================== out1 pass A: T = rna(s) @ B3p^T   (M=8192, N=4096, K=64) =====================
// CTA 128 x 128, 8 warps 4M x 2N, warp tile 32 x 64. Single K pass (2 interleaved 32-chunks).
__global__ __launch_bounds__(256) void tgemm_kernel(const float* __restrict__ x) {
    extern __shared__ __align__(16) float dsm[];
    float* As = dsm;             // [128][72]
    float* Bs = dsm + 128 * 72;  // [128][72]

    const int tid = threadIdx.x, lane = tid & 31, wid = tid >> 5;
    const int warpM = wid & 3, warpN = wid >> 2;
    const int g = lane >> 2, q4 = lane & 3;
    const int z0 = blockIdx.x * 128, n0 = blockIdx.y * 128;
    const int r = tid >> 1, h = tid & 1;

    // stage A: rna(s) rows z0.., cols u = h*32..+31, interleaved pair layout
    {
        const float* src = x + (size_t)(z0 + r) * 256 + h * 32;
        float* dst = As + r * 72 + h * 36;
        #pragma unroll
        for (int je = 0; je < 8; je += 2) {
            float4 v0 = *(const float4*)(src + je * 4);
            float4 v1 = *(const float4*)(src + je * 4 + 4);
            *(float2*)(dst + je * 4 + 0) = make_float2(u2f(rna(v0.x)), u2f(rna(v1.x)));
            *(float2*)(dst + je * 4 + 2) = make_float2(u2f(rna(v0.y)), u2f(rna(v1.y)));
            *(float2*)(dst + je * 4 + 4) = make_float2(u2f(rna(v0.z)), u2f(rna(v1.z)));
            *(float2*)(dst + je * 4 + 6) = make_float2(u2f(rna(v0.w)), u2f(rna(v1.w)));
        }
    }
    // stage B: g_B3p rows n0.., cols u (already tf32)
    {
        const float* src = g_B3p + (size_t)(n0 + r) * 64 + h * 32;
        float* dst = Bs + r * 72 + h * 36;
        #pragma unroll
        for (int je = 0; je < 8; je += 2) {
            float4 v0 = *(const float4*)(src + je * 4);
            float4 v1 = *(const float4*)(src + je * 4 + 4);
            *(float2*)(dst + je * 4 + 0) = make_float2(v0.x, v1.x);
            *(float2*)(dst + je * 4 + 2) = make_float2(v0.y, v1.y);
            *(float2*)(dst + je * 4 + 4) = make_float2(v0.z, v1.z);
            *(float2*)(dst + je * 4 + 6) = make_float2(v0.w, v1.w);
        }
    }
    __syncthreads();

    float acc[2][8][4];
    #pragma unroll
    for (int mt = 0; mt < 2; ++mt)
        #pragma unroll
        for (int nt = 0; nt < 8; ++nt)
            #pragma unroll
            for (int j = 0; j < 4; ++j) acc[mt][nt][j] = 0.0f;

    #pragma unroll
    for (int ch = 0; ch < 2; ++ch) {
        #pragma unroll
        for (int k8 = 0; k8 < 4; ++k8) {
            int ko = ch * 36 + k8 * 8 + q4 * 2;
            uint32_t a[2][4], b[8][2];
            #pragma unroll
            for (int mt = 0; mt < 2; ++mt) {
                float2 lo = *(const float2*)(As + (warpM * 32 + mt * 16 + g) * 72 + ko);
                float2 hi = *(const float2*)(As + (warpM * 32 + mt * 16 + 8 + g) * 72 + ko);
                a[mt][0] = __float_as_uint(lo.x); a[mt][1] = __float_as_uint(hi.x);
                a[mt][2] = __float_as_uint(lo.y); a[mt][3] = __float_as_uint(hi.y);
            }
            #pragma unroll
            for (int nt = 0; nt < 8; ++nt) {
                float2 bv = *(const float2*)(Bs + (warpN * 64 + nt * 8 + g) * 72 + ko);
                b[nt][0] = __float_as_uint(bv.x); b[nt][1] = __float_as_uint(bv.y);
            }
            #pragma unroll
            for (int mt = 0; mt < 2; ++mt)
                #pragma unroll
                for (int nt = 0; nt < 8; ++nt)
                    mma8(acc[mt][nt], a[mt], b[nt]);
        }
    }

    #pragma unroll
    for (int mt = 0; mt < 2; ++mt) {
        int za = z0 + warpM * 32 + mt * 16 + g;
        #pragma unroll
        for (int nt = 0; nt < 8; ++nt) {
            int n = n0 + warpN * 64 + nt * 8 + q4 * 2;
            *(float2*)(g_T + (size_t)za * 4096 + n)       = make_float2(acc[mt][nt][0], acc[mt][nt][1]);
            *(float2*)(g_T + (size_t)(za + 8) * 4096 + n) = make_float2(acc[mt][nt][2], acc[mt][nt][3]);
        }
    }
}

// ===================== out1 pass B: out1[z,w,k] = (1/64) * sum_m T[z,m*64+w] * v[z,m,k] =========
__global__ __launch_bounds__(256) void contract_kernel(const float* __restrict__ x,
                                                       float* __restrict__ out) {
    int tid = threadIdx.x;
    int wp = tid >> 5, lane = tid & 31;
    size_t z = (size_t)blockIdx.x * 8 + wp;
    const float* Trow = g_T + z * 4096;
    const float* vp = x + z * 256 + 64;
    float a00 = 0.f, a01 = 0.f, a02 = 0.f, a10 = 0.f, a11 = 0.f, a12 = 0.f;
    #pragma unroll 4
    for (int m = 0; m < 64; ++m) {
        float t0 = Trow[m * 64 + lane];
        float t1 = Trow[m * 64 + 32 + lane];
        float vx = vp[m * 3 + 0], vy = vp[m * 3 + 1], vz = vp[m * 3 + 2];
        a00 += t0 * vx; a01 += t0 * vy; a02 += t0 * vz;
        a10 += t1 * vx; a11 += t1 * vy; a12 += t1 * vz;
    }
    float* base = out + z * NOUT + 64;
    const float sc = 0.015625f;   // 1/64 == C3/sqrt(3)
    base[lane * 3 + 0] = a00 * sc; base[lane * 3 + 1] = a01 * sc; base[lane * 3 + 2] = a02 * sc;
    base[(lane + 32) * 3 + 0] = a10 * sc; base[(lane + 32) * 3 + 1] = a11 * sc; base[(lane + 32) * 3 + 2] = a12 * sc;
}

// ===================== launch =====================
extern "C" void kernel_launch(void* const* d_in, const int* in_sizes, int n_in,
                              void* d_out, int out_size) {
    const float* x  = (const float*)d_in[0];
    const float* w1 = (const float*)d_in[1];
    const float* w2 = (const float*)d_in[2];
    const float* w3 = (const float*)d_in[3];
    const float* w4 = (const float*)d_in[4];
    const float* w5 = (const float*)d_in[5];
    const float* w6 = (const float*)d_in[6];
    float* out = (float*)d_out;

    float c1  = (float)sqrt(1.0 / 4160.0);     // C1
    float c2  = (float)sqrt(1.0 / 12480.0);    // C2 == C4/sqrt(3)
    float c5s = (float)sqrt(1.0 / 62400.0);    // C5/sqrt(3)
    float c6s = (float)sqrt(1.0 / 4032.0);     // C6/sqrt(6)

    const int MAIN_SMEM = (2 * 128 * 36 + 2 * 64 * 36 + 128 * 257) * 4 + QP * 2;  // 190,912
    const int TG_SMEM   = 2 * 128 * 72 * 4;                                        //  73,728
    cudaFuncSetAttribute(main_kernel,  cudaFuncAttributeMaxDynamicSharedMemorySize, MAIN_SMEM);
    cudaFuncSetAttribute(tgemm_kernel, cudaFuncAttributeMaxDynamicSharedMemorySize, TG_SMEM);

    cudaMemsetAsync(d_out, 0, (size_t)out_size * sizeof(float));
    init_tables_kernel<<<1, 64>>>();
    const int NTOT = 64 * 4160 + 64 * 2016 + 4096 * 64;
    prep_w_kernel<<<(NTOT + 255) / 256, 256>>>(w1, w2, w3, w4, w5, w6, c1, c2, c5s, c6s);

    tgemm_kernel<<<dim3(64, 32), 256, TG_SMEM>>>(x);          // T = s @ w3
    main_kernel<<<dim3(64, 5), 256, MAIN_SMEM>>>(x, out);     // out0 (2 K-halves) + out2 (3 comps)
    contract_kernel<<<ZDIM / 8, 256>>>(x, out);               // out1
}

// round 7
// speedup vs baseline: 1.1736x; 1.1660x over previous
#include <cuda_runtime.h>
#include <cstdint>
#include <cmath>

#define ZDIM 8192
#define QP   2016
#define NOUT 448

// ===================== device globals (no allocation) =====================
static __device__ float g_B0t[64 * 4160];          // out0 weights [w][k], prescaled + tf32
static __device__ float g_B6t[64 * 2016];          // out2 weights [w][q], prescaled + tf32
static __device__ float g_B3p[4096 * 64];          // out1 weights [n=(m*64+w)][u], tf32
static __device__ float g_T[(size_t)ZDIM * 4096];  // T = s @ w3 scratch [z][m*64+w]
static __device__ unsigned short g_uv[QP];         // packed (u | t<<8)

// ===================== helpers =====================
__device__ __forceinline__ uint32_t rna(float f) {
    uint32_t r; asm("cvt.rna.tf32.f32 %0, %1;" : "=r"(r) : "f"(f)); return r;
}
__device__ __forceinline__ float u2f(uint32_t u) { return __uint_as_float(u); }
__device__ __forceinline__ void mma8(float* c, const uint32_t* a, const uint32_t* b) {
    asm volatile("mma.sync.aligned.m16n8k8.row.col.f32.tf32.tf32.f32 "
        "{%0,%1,%2,%3}, {%4,%5,%6,%7}, {%8,%9}, {%0,%1,%2,%3};"
        : "+f"(c[0]), "+f"(c[1]), "+f"(c[2]), "+f"(c[3])
        : "r"(a[0]), "r"(a[1]), "r"(a[2]), "r"(a[3]), "r"(b[0]), "r"(b[1]));
}

// ===================== setup kernels =====================
__global__ void init_tables_kernel() {
    int u = threadIdx.x;
    if (u < 63) {
        int idx = u * 63 - (u * (u - 1)) / 2;
        for (int v = u + 1; v < 64; ++v) {
            g_uv[idx] = (unsigned short)(u | (v << 8));
            ++idx;
        }
    }
}

__global__ void prep_w_kernel(const float* __restrict__ w1, const float* __restrict__ w2,
                              const float* __restrict__ w3, const float* __restrict__ w4,
                              const float* __restrict__ w5, const float* __restrict__ w6,
                              float c1, float c2, float c5s, float c6s) {
    int i = blockIdx.x * blockDim.x + threadIdx.x;
    const int N0 = 64 * 4160, N1 = 64 * 2016, N2 = 4096 * 64;
    if (i < N0) {
        int w = i / 4160, k = i - w * 4160;
        float v;
        if (k < 2016)      v = c1  * w1[k * 64 + w];
        else if (k < 2080) v = c2  * w2[(k - 2016) * 64 + w];
        else if (k < 4096) v = c2  * w4[(k - 2080) * 64 + w];
        else               v = c5s * w5[(k - 4096) * 64 + w];
        g_B0t[i] = u2f(rna(v));
    } else if (i < N0 + N1) {
        int j = i - N0;
        int w = j / 2016, q = j - w * 2016;
        g_B6t[j] = u2f(rna(c6s * w6[q * 64 + w]));
    } else if (i < N0 + N1 + N2) {
        int j = i - N0 - N1;
        int n = j >> 6, u = j & 63;                  // n = m*64+w
        g_B3p[j] = u2f(rna(w3[(size_t)u * 4096 + n]));
    }
}

// ===================== main fused kernel (templated, 512 threads) =====================
// CTA 128z x 64w, 16 warps, warp tile 32M x 16N (warps 4M x 4N).
// MODE 0: out0; blockIdx.y = K-split 0..3 (chunks 33/33/32/32). atomicAdd epilogue.
// MODE 2: out2; blockIdx.y = cross component 0..2, K=2016 (63 chunks). direct store.
template<int MODE>
__global__ __launch_bounds__(512) void main_kernel(const float* __restrict__ x,
                                                   float* __restrict__ out) {
    extern __shared__ __align__(16) float dsm[];
    float* As = dsm;                                 // [2][128][36] pair-interleaved
    float* Bs = dsm + 2 * 128 * 36;                  // [2][64][36]  plain
    float* xs = Bs + 2 * 64 * 36;                    // [128][257]
    unsigned short* uvs = (unsigned short*)(xs + 128 * 257);

    const int tid = threadIdx.x, lane = tid & 31, wid = tid >> 5;
    const int warpM = wid & 3, warpN = wid >> 2;     // 4 x 4
    const int g = lane >> 2, q4 = lane & 3;
    const int z0 = blockIdx.x * 128;
    const int y = blockIdx.y;

    int NCH, kofs, kz = 0;
    if (MODE == 0) {
        const int ncha[4] = {33, 33, 32, 32};
        const int kfa[4] = {0, 1056, 2112, 3136};
        NCH = ncha[y]; kofs = kfa[y];
    } else {
        NCH = 63; kofs = 0; kz = y;
    }
    const int LDB = (MODE == 0) ? 4160 : 2016;
    const float* Bsrc = (MODE == 0) ? g_B0t : g_B6t;
    const int ca = (kz + 1) % 3, cb = (kz + 2) % 3;

    // ---- stage x tile + pair table ----
    {
        int col = tid & 255, r0 = tid >> 8;
        #pragma unroll 4
        for (int j = r0; j < 128; j += 2)
            xs[j * 257 + col] = x[(size_t)(z0 + j) * 256 + col];
    }
    for (int i = tid; i < QP; i += 512) uvs[i] = g_uv[i];

    const int row = tid >> 2, h = tid & 3;           // 128 rows x 4 k8-groups
    const float* xr = xs + row * 257;
    const int brow = tid >> 3, bc4 = tid & 7;        // B stage: 64 rows x 8 float4
    const float* bbase = Bsrc + (size_t)brow * LDB + kofs + bc4 * 4;

    float acc[2][2][4];
    #pragma unroll
    for (int mt = 0; mt < 2; ++mt)
        #pragma unroll
        for (int nt = 0; nt < 2; ++nt)
            #pragma unroll
            for (int j = 0; j < 4; ++j) acc[mt][nt][j] = 0.0f;

    uint32_t fr[8];
    float4 rb;

    // ---- feature generation (8 features, k8-block h of chunk CC) ----
    #define GEN(CC) do {                                                        \
        int kbase = kofs + (CC) * 32 + h * 8;                                   \
        _Pragma("unroll")                                                       \
        for (int i = 0; i < 8; ++i) {                                           \
            int k = kbase + i;                                                  \
            float f;                                                            \
            if (MODE == 0) {                                                    \
                if (k < 2016) {                                                 \
                    int uv = uvs[k];                                            \
                    f = xr[uv & 255] * xr[uv >> 8];                             \
                } else if (k < 2080) {                                          \
                    float s = xr[k - 2016]; f = s * s;                          \
                } else if (k < 4096) {                                          \
                    int uv = uvs[k - 2080];                                     \
                    const float* a = xr + 64 + 3 * (uv & 255);                  \
                    const float* b = xr + 64 + 3 * (uv >> 8);                   \
                    f = a[0] * b[0] + a[1] * b[1] + a[2] * b[2];                \
                } else {                                                        \
                    const float* a = xr + 64 + 3 * (k - 4096);                  \
                    f = a[0] * a[0] + a[1] * a[1] + a[2] * a[2];                \
                }                                                               \
            } else {                                                            \
                int uv = uvs[k];                                                \
                const float* a = xr + 64 + 3 * (uv & 255);                      \
                const float* b = xr + 64 + 3 * (uv >> 8);                       \
                f = a[ca] * b[cb] - a[cb] * b[ca];                              \
            }                                                                   \
            fr[i] = rna(f);                                                     \
        }                                                                       \
    } while (0)

    #define STORE_A(CC) do {                                                    \
        float* ap = As + ((CC) & 1) * (128 * 36) + row * 36 + h * 8;            \
        _Pragma("unroll")                                                       \
        for (int j = 0; j < 4; ++j)                                             \
            *(float2*)(ap + j * 2) = make_float2(u2f(fr[j]), u2f(fr[j + 4]));   \
    } while (0)

    #define STORE_B(CC) do {                                                    \
        *(float4*)(Bs + ((CC) & 1) * (64 * 36) + brow * 36 + bc4 * 4) = rb;     \
    } while (0)

    // prologue: chunk 0
    __syncthreads();
    rb = *(const float4*)(bbase);
    GEN(0);
    STORE_A(0);
    STORE_B(0);
    __syncthreads();

    for (int c = 0; c < NCH; ++c) {
        bool more = (c + 1 < NCH);
        if (more) {
            rb = *(const float4*)(bbase + (c + 1) * 32);
            GEN(c + 1);
            STORE_A(c + 1);
        }
        {
            const float* Ab = As + (c & 1) * (128 * 36) + (warpM * 32) * 36;
            const float* Bb = Bs + (c & 1) * (64 * 36) + (warpN * 16) * 36;
            #pragma unroll
            for (int k8 = 0; k8 < 4; ++k8) {
                uint32_t a[2][4], b[2][2];
                #pragma unroll
                for (int mt = 0; mt < 2; ++mt) {
                    float2 lo = *(const float2*)(Ab + (mt * 16 + g) * 36 + k8 * 8 + q4 * 2);
                    float2 hi = *(const float2*)(Ab + (mt * 16 + 8 + g) * 36 + k8 * 8 + q4 * 2);
                    a[mt][0] = __float_as_uint(lo.x); a[mt][1] = __float_as_uint(hi.x);
                    a[mt][2] = __float_as_uint(lo.y); a[mt][3] = __float_as_uint(hi.y);
                }
                #pragma unroll
                for (int nt = 0; nt < 2; ++nt) {
                    const float* bp = Bb + (nt * 8 + g) * 36 + k8 * 8;
                    b[nt][0] = __float_as_uint(bp[q4]);
                    b[nt][1] = __float_as_uint(bp[q4 + 4]);
                }
                #pragma unroll
                for (int mt = 0; mt < 2; ++mt)
                    #pragma unroll
                    for (int nt = 0; nt < 2; ++nt)
                        mma8(acc[mt][nt], a[mt], b[nt]);
            }
        }
        if (more) STORE_B(c + 1);
        __syncthreads();
    }

    // ---- epilogue ----
    #pragma unroll
    for (int mt = 0; mt < 2; ++mt) {
        int za = z0 + warpM * 32 + mt * 16 + g;
        int zb = za + 8;
        #pragma unroll
        for (int nt = 0; nt < 2; ++nt) {
            int col = warpN * 16 + nt * 8 + q4 * 2;
            if (MODE == 0) {
                atomicAdd(out + (size_t)za * NOUT + col,     acc[mt][nt][0]);
                atomicAdd(out + (size_t)za * NOUT + col + 1, acc[mt][nt][1]);
                atomicAdd(out + (size_t)zb * NOUT + col,     acc[mt][nt][2]);
                atomicAdd(out + (size_t)zb * NOUT + col + 1, acc[mt][nt][3]);
            } else {
                out[(size_t)za * NOUT + 256 + col * 3 + kz]       = acc[mt][nt][0];
                out[(size_t)za * NOUT + 256 + (col + 1) * 3 + kz] = acc[mt][nt][1];
                out[(size_t)zb * NOUT + 256 + col * 3 + kz]       = acc[mt][nt][2];
                out[(size_t)zb * NOUT + 256 + (col + 1) * 3 + kz] = acc[mt][nt][3];
            }
        }
    }
    #undef GEN
    #undef STORE_A
    #undef STORE_B
}

// ===================== out1 pass A: T = rna(s) @ B3p^T   (M=8192, N=4096, K=64) ==========
__global__ __launch_bounds__(256) void tgemm_kernel(const float* __restrict__ x) {
    extern __shared__ __align__(16) float dsm[];
    float* As = dsm;             // [128][72]
    float* Bs = dsm + 128 * 72;  // [128][72]

    const int tid = threadIdx.x, lane = tid & 31, wid = tid >> 5;
    const int warpM = wid & 3, warpN = wid >> 2;
    const int g = lane >> 2, q4 = lane & 3;
    const int z0 = blockIdx.x * 128, n0 = blockIdx.y * 128;
    const int r = tid >> 1, h = tid & 1;

    {
        const float* src = x + (size_t)(z0 + r) * 256 + h * 32;
        float* dst = As + r * 72 + h * 36;
        #pragma unroll
        for (int je = 0; je < 8; je += 2) {
            float4 v0 = *(const float4*)(src + je * 4);
            float4 v1 = *(const float4*)(src + je * 4 + 4);
            *(float2*)(dst + je * 4 + 0) = make_float2(u2f(rna(v0.x)), u2f(rna(v1.x)));
            *(float2*)(dst + je * 4 + 2) = make_float2(u2f(rna(v0.y)), u2f(rna(v1.y)));
            *(float2*)(dst + je * 4 + 4) = make_float2(u2f(rna(v0.z)), u2f(rna(v1.z)));
            *(float2*)(dst + je * 4 + 6) = make_float2(u2f(rna(v0.w)), u2f(rna(v1.w)));
        }
    }
    {
        const float* src = g_B3p + (size_t)(n0 + r) * 64 + h * 32;
        float* dst = Bs + r * 72 + h * 36;
        #pragma unroll
        for (int je = 0; je < 8; je += 2) {
            float4 v0 = *(const float4*)(src + je * 4);
            float4 v1 = *(const float4*)(src + je * 4 + 4);
            *(float2*)(dst + je * 4 + 0) = make_float2(v0.x, v1.x);
            *(float2*)(dst + je * 4 + 2) = make_float2(v0.y, v1.y);
            *(float2*)(dst + je * 4 + 4) = make_float2(v0.z, v1.z);
            *(float2*)(dst + je * 4 + 6) = make_float2(v0.w, v1.w);
        }
    }
    __syncthreads();

    float acc[2][8][4];
    #pragma unroll
    for (int mt = 0; mt < 2; ++mt)
        #pragma unroll
        for (int nt = 0; nt < 8; ++nt)
            #pragma unroll
            for (int j = 0; j < 4; ++j) acc[mt][nt][j] = 0.0f;

    #pragma unroll
    for (int ch = 0; ch < 2; ++ch) {
        #pragma unroll
        for (int k8 = 0; k8 < 4; ++k8) {
            int ko = ch * 36 + k8 * 8 + q4 * 2;
            uint32_t a[2][4], b[8][2];
            #pragma unroll
            for (int mt = 0; mt < 2; ++mt) {
                float2 lo = *(const float2*)(As + (warpM * 32 + mt * 16 + g) * 72 + ko);
                float2 hi = *(const float2*)(As + (warpM * 32 + mt * 16 + 8 + g) * 72 + ko);
                a[mt][0] = __float_as_uint(lo.x); a[mt][1] = __float_as_uint(hi.x);
                a[mt][2] = __float_as_uint(lo.y); a[mt][3] = __float_as_uint(hi.y);
            }
            #pragma unroll
            for (int nt = 0; nt < 8; ++nt) {
                float2 bv = *(const float2*)(Bs + (warpN * 64 + nt * 8 + g) * 72 + ko);
                b[nt][0] = __float_as_uint(bv.x); b[nt][1] = __float_as_uint(bv.y);
            }
            #pragma unroll
            for (int mt = 0; mt < 2; ++mt)
                #pragma unroll
                for (int nt = 0; nt < 8; ++nt)
                    mma8(acc[mt][nt], a[mt], b[nt]);
        }
    }

    #pragma unroll
    for (int mt = 0; mt < 2; ++mt) {
        int za = z0 + warpM * 32 + mt * 16 + g;
        #pragma unroll
        for (int nt = 0; nt < 8; ++nt) {
            int n = n0 + warpN * 64 + nt * 8 + q4 * 2;
            *(float2*)(g_T + (size_t)za * 4096 + n)       = make_float2(acc[mt][nt][0], acc[mt][nt][1]);
            *(float2*)(g_T + (size_t)(za + 8) * 4096 + n) = make_float2(acc[mt][nt][2], acc[mt][nt][3]);
        }
    }
}

// ===================== out1 pass B: out1[z,w,k] = (1/64) * sum_m T[z,m*64+w] * v[z,m,k] ====
__global__ __launch_bounds__(256) void contract_kernel(const float* __restrict__ x,
                                                       float* __restrict__ out) {
    int tid = threadIdx.x;
    int wp = tid >> 5, lane = tid & 31;
    size_t z = (size_t)blockIdx.x * 8 + wp;
    const float* Trow = g_T + z * 4096;
    const float* vp = x + z * 256 + 64;
    float a00 = 0.f, a01 = 0.f, a02 = 0.f, a10 = 0.f, a11 = 0.f, a12 = 0.f;
    #pragma unroll 4
    for (int m = 0; m < 64; ++m) {
        float t0 = Trow[m * 64 + lane];
        float t1 = Trow[m * 64 + 32 + lane];
        float vx = vp[m * 3 + 0], vy = vp[m * 3 + 1], vz = vp[m * 3 + 2];
        a00 += t0 * vx; a01 += t0 * vy; a02 += t0 * vz;
        a10 += t1 * vx; a11 += t1 * vy; a12 += t1 * vz;
    }
    float* base = out + z * NOUT + 64;
    const float sc = 0.015625f;
    base[lane * 3 + 0] = a00 * sc; base[lane * 3 + 1] = a01 * sc; base[lane * 3 + 2] = a02 * sc;
    base[(lane + 32) * 3 + 0] = a10 * sc; base[(lane + 32) * 3 + 1] = a11 * sc; base[(lane + 32) * 3 + 2] = a12 * sc;
}

// ===================== launch =====================
extern "C" void kernel_launch(void* const* d_in, const int* in_sizes, int n_in,
                              void* d_out, int out_size) {
    const float* x  = (const float*)d_in[0];
    const float* w1 = (const float*)d_in[1];
    const float* w2 = (const float*)d_in[2];
    const float* w3 = (const float*)d_in[3];
    const float* w4 = (const float*)d_in[4];
    const float* w5 = (const float*)d_in[5];
    const float* w6 = (const float*)d_in[6];
    float* out = (float*)d_out;

    float c1  = (float)sqrt(1.0 / 4160.0);     // C1
    float c2  = (float)sqrt(1.0 / 12480.0);    // C2 == C4/sqrt(3)
    float c5s = (float)sqrt(1.0 / 62400.0);    // C5/sqrt(3)
    float c6s = (float)sqrt(1.0 / 4032.0);     // C6/sqrt(6)

    const int MAIN_SMEM = (2 * 128 * 36 + 2 * 64 * 36 + 128 * 257) * 4 + QP * 2;  // 190,912
    const int TG_SMEM   = 2 * 128 * 72 * 4;                                        //  73,728
    cudaFuncSetAttribute(main_kernel<0>, cudaFuncAttributeMaxDynamicSharedMemorySize, MAIN_SMEM);
    cudaFuncSetAttribute(main_kernel<2>, cudaFuncAttributeMaxDynamicSharedMemorySize, MAIN_SMEM);
    cudaFuncSetAttribute(tgemm_kernel,   cudaFuncAttributeMaxDynamicSharedMemorySize, TG_SMEM);

    cudaMemsetAsync(d_out, 0, (size_t)out_size * sizeof(float));
    init_tables_kernel<<<1, 64>>>();
    const int NTOT = 64 * 4160 + 64 * 2016 + 4096 * 64;
    prep_w_kernel<<<(NTOT + 255) / 256, 256>>>(w1, w2, w3, w4, w5, w6, c1, c2, c5s, c6s);

    main_kernel<2><<<dim3(64, 3), 512, MAIN_SMEM>>>(x, out);  // out2 (3 components, 63 chunks)
    main_kernel<0><<<dim3(64, 4), 512, MAIN_SMEM>>>(x, out);  // out0 (split-K = 4)
    tgemm_kernel<<<dim3(64, 32), 256, TG_SMEM>>>(x);          // T = s @ w3
    contract_kernel<<<ZDIM / 8, 256>>>(x, out);               // out1
}